// round 15
// baseline (speedup 1.0000x reference)
#include <cuda_runtime.h>
#include <cuda_bf16.h>
#include <cstdint>
#include <cstddef>

// ---------------------------------------------------------------------------
// Problem constants
// ---------------------------------------------------------------------------
#define cB 32
#define cS 2304
#define cD 1280
#define cDEPTH 6
#define cH 16
#define cHD 96
#define cL 64
#define cI 5120
#define cT (cS + cL)      /* 2368 */
#define cHHD (cH * cHD)   /* 1536 */
#define cEPS 1e-5f
#define cMCTX (cB * cS)   /* 73728 ctx rows */
#define cML (cB * cL)     /* 2048 latent rows */
#define cMB (cMCTX / 128) /* 576 ctx row-blocks */
#define cNCC (cD / 32)    /* 40 k-chunks for Kdim=1280 */

typedef __nv_bfloat16 bf16;

// Tiled blob: (row>>7, k>>5) chunk of 128 rows x 32 elems, stored 128x40 elems
#define TBE(blocks, nc) ((size_t)(blocks) * (nc) * 5120)

// ---------------------------------------------------------------------------
// Scratch (device globals: allocation-free rule)
// ---------------------------------------------------------------------------
__device__ bf16 g_ctxT_hi[TBE(cMB, 40)], g_ctxT_lo[TBE(cMB, 40)];
__device__ bf16 g_latlnT_hi[TBE(16, 40)], g_latlnT_lo[TBE(16, 40)];
__device__ bf16 g_attT_hi[TBE(16, 48)], g_attT_lo[TBE(16, 48)];
__device__ bf16 g_mlpT_hi[TBE(16, 160)], g_mlpT_lo[TBE(16, 160)];
__device__ bf16 g_wkcT_hi[TBE(12, 40)], g_wkcT_lo[TBE(12, 40)];
__device__ bf16 g_wvcT_hi[TBE(12, 40)], g_wvcT_lo[TBE(12, 40)];
__device__ bf16 g_wqT_hi[TBE(12, 40)],  g_wqT_lo[TBE(12, 40)];
__device__ bf16 g_wklT_hi[TBE(12, 40)], g_wklT_lo[TBE(12, 40)];
__device__ bf16 g_wvlT_hi[TBE(12, 40)], g_wvlT_lo[TBE(12, 40)];
__device__ bf16 g_woT_hi[TBE(10, 48)],  g_woT_lo[TBE(10, 48)];
__device__ bf16 g_wfcT_hi[TBE(40, 40)], g_wfcT_lo[TBE(40, 40)];
__device__ bf16 g_wcpT_hi[TBE(10, 160)], g_wcpT_lo[TBE(10, 160)];
// linear buffers
__device__ bf16 g_V_hi[(size_t)cB * cT * cHHD], g_V_lo[(size_t)cB * cT * cHHD];
__device__ float g_biasQ[cHHD], g_biasKc[cHHD], g_biasKl[cHHD];
__device__ float g_biasVc[cHHD], g_biasVl[cHHD], g_biasFc[cI];
__device__ float g_lat[cML * cD];
__device__ float g_Q[cML * cHHD];
__device__ float g_K[(size_t)cB * cT * cHHD];

// ---------------------------------------------------------------------------
// PTX helpers (base sm_90 features only)
// ---------------------------------------------------------------------------
__device__ __forceinline__ uint32_t smem_u32(const void* p) {
  uint32_t a;
  asm("{ .reg .u64 t; cvta.to.shared.u64 t, %1; cvt.u32.u64 %0, t; }"
      : "=r"(a) : "l"(p));
  return a;
}
__device__ __forceinline__ void cp_async16(uint32_t saddr, const void* gptr) {
  asm volatile("cp.async.cg.shared.global [%0], [%1], 16;" ::"r"(saddr),
               "l"(gptr)
               : "memory");
}
#define CP_COMMIT() asm volatile("cp.async.commit_group;" ::: "memory")
#define CP_WAIT(N) asm volatile("cp.async.wait_group %0;" ::"n"(N) : "memory")

__device__ __forceinline__ void bulk_g2s(uint32_t dst, const void* src,
                                         uint32_t bytes, uint32_t bar) {
  asm volatile(
      "cp.async.bulk.shared::cta.global.mbarrier::complete_tx::bytes "
      "[%0], [%1], %2, [%3];"
      :: "r"(dst), "l"(src), "r"(bytes), "r"(bar)
      : "memory");
}
#define MBAR_INIT(mb, n)                                                   \
  asm volatile("mbarrier.init.shared.b64 [%0], %1;" ::"r"((uint32_t)(mb)), \
               "r"((uint32_t)(n))                                          \
               : "memory")
#define MBAR_EXPECT_TX(mb, n)                                              \
  asm volatile("mbarrier.arrive.expect_tx.shared.b64 _, [%0], %1;" ::"r"(  \
                   (uint32_t)(mb)),                                        \
               "r"((uint32_t)(n))                                          \
               : "memory")
#define MBAR_ARRIVE(mb)                                                    \
  asm volatile("mbarrier.arrive.shared.b64 _, [%0];" ::"r"((uint32_t)(mb)) \
               : "memory")
#define MBAR_WAIT(mb, par) do {                                              \
  uint32_t _mb = (uint32_t)(mb), _p = (uint32_t)(par), _d;                   \
  asm volatile(                                                              \
      "{\n\t.reg .pred p;\n\t"                                               \
      "mbarrier.try_wait.parity.acquire.cta.shared::cta.b64 p, [%1], %2;\n\t"\
      "selp.b32 %0, 1, 0, p;\n\t}"                                           \
      : "=r"(_d) : "r"(_mb), "r"(_p) : "memory");                            \
  if (!_d) {                                                                 \
    asm volatile(                                                            \
        "{\n\t.reg .pred P1;\n\t"                                            \
        "W1_%=:\n\t"                                                         \
        "mbarrier.try_wait.parity.acquire.cta.shared::cta.b64 P1, [%0], %1, 0x989680;\n\t" \
        "@P1 bra.uni W2_%=;\n\tbra.uni W1_%=;\n\tW2_%=:\n\t}"                \
        :: "r"(_mb), "r"(_p) : "memory");                                    \
  }                                                                          \
} while (0)

__device__ __forceinline__ void ldsm_x4(uint32_t* d, uint32_t addr) {
  asm volatile("ldmatrix.sync.aligned.m8n8.x4.shared.b16 {%0,%1,%2,%3},[%4];"
               : "=r"(d[0]), "=r"(d[1]), "=r"(d[2]), "=r"(d[3])
               : "r"(addr));
}
__device__ __forceinline__ void ldsm_x2(uint32_t* d, uint32_t addr) {
  asm volatile("ldmatrix.sync.aligned.m8n8.x2.shared.b16 {%0,%1},[%2];"
               : "=r"(d[0]), "=r"(d[1])
               : "r"(addr));
}
__device__ __forceinline__ void ldsm_x2_trans(uint32_t* d, uint32_t addr) {
  asm volatile("ldmatrix.sync.aligned.m8n8.x2.trans.shared.b16 {%0,%1},[%2];"
               : "=r"(d[0]), "=r"(d[1])
               : "r"(addr));
}
__device__ __forceinline__ void mma16816(float* c, const uint32_t* a,
                                         const uint32_t* b) {
  asm volatile(
      "mma.sync.aligned.m16n8k16.row.col.f32.bf16.bf16.f32 "
      "{%0,%1,%2,%3},{%4,%5,%6,%7},{%8,%9},{%0,%1,%2,%3};"
      : "+f"(c[0]), "+f"(c[1]), "+f"(c[2]), "+f"(c[3])
      : "r"(a[0]), "r"(a[1]), "r"(a[2]), "r"(a[3]), "r"(b[0]), "r"(b[1]));
}

// Fast exp on the FMA pipe (degree-6 2^f poly; rel err ~8e-6).
__device__ __forceinline__ float fexp(float x) {
  x = fmaxf(x, -87.0f);
  float t = x * 1.4426950408889634f;
  float fi = floorf(t);
  float f = t - fi;
  float p = 1.54035304e-4f;
  p = fmaf(p, f, 1.33335581e-3f);
  p = fmaf(p, f, 9.61812911e-3f);
  p = fmaf(p, f, 5.55041087e-2f);
  p = fmaf(p, f, 2.40226507e-1f);
  p = fmaf(p, f, 6.93147181e-1f);
  p = fmaf(p, f, 1.0f);
  int i = (int)fi;
  return p * __int_as_float((i + 127) << 23);
}

// ---------------------------------------------------------------------------
// Fused K+V GEMM, bulk loader + empty-barrier pipeline (unchanged R13).
// ---------------------------------------------------------------------------
#define FB_STRIDE 40
#define FB_ARR 10240
#define FB_CHUNK (6 * FB_ARR)
#define FB_HDR 1024
#define FB_SMEM (FB_HDR + 3 * FB_CHUNK)

__global__ __launch_bounds__(512) void fused_kv_bulk(
    const bf16* __restrict__ AThi, const bf16* __restrict__ ATlo,
    const bf16* __restrict__ BkThi, const bf16* __restrict__ BkTlo,
    const bf16* __restrict__ BvThi, const bf16* __restrict__ BvTlo,
    const float* __restrict__ biasK, const float* __restrict__ biasV,
    float* __restrict__ Kout, bf16* __restrict__ Vhi, bf16* __restrict__ Vlo,
    int rpbIn, int rpbOut, int rowOff) {
  extern __shared__ char sm[];
  const uint32_t sb = smem_u32(sm);
  const int tid = threadIdx.x, lane = tid & 31, wid = tid >> 5;
  const int grp = wid >> 3;
  const int gw = wid & 7;
  const int wm = gw & 1, wn = gw >> 1;
  const int mb = blockIdx.y, nb = blockIdx.x;
  const int m0 = mb * 128, n0 = nb * 128;

  const char* srcs[6];
  srcs[0] = (const char*)AThi + (size_t)mb * cNCC * FB_ARR;
  srcs[1] = (const char*)ATlo + (size_t)mb * cNCC * FB_ARR;
  srcs[2] = (const char*)BkThi + (size_t)nb * cNCC * FB_ARR;
  srcs[3] = (const char*)BkTlo + (size_t)nb * cNCC * FB_ARR;
  srcs[4] = (const char*)BvThi + (size_t)nb * cNCC * FB_ARR;
  srcs[5] = (const char*)BvTlo + (size_t)nb * cNCC * FB_ARR;

  if (tid == 0) {
    MBAR_INIT(sb + 0, 1);
    MBAR_INIT(sb + 8, 1);
    MBAR_INIT(sb + 16, 1);
    MBAR_INIT(sb + 24, 16);
    MBAR_INIT(sb + 32, 16);
    MBAR_INIT(sb + 40, 16);
  }
  __syncthreads();

  auto issue = [&](int c) {
    int s = c % 3;
    uint32_t bar = sb + s * 8;
    MBAR_EXPECT_TX(bar, FB_CHUNK);
    uint32_t dst = sb + FB_HDR + s * FB_CHUNK;
#pragma unroll
    for (int a = 0; a < 6; a++)
      bulk_g2s(dst + a * FB_ARR, srcs[a] + (size_t)c * FB_ARR, FB_ARR, bar);
  };
  if (tid == 0) { issue(0); issue(1); }

  float acc[4][4][4];
#pragma unroll
  for (int mt = 0; mt < 4; mt++)
#pragma unroll
    for (int nt = 0; nt < 4; nt++)
#pragma unroll
      for (int j = 0; j < 4; j++) acc[mt][nt][j] = 0.f;

  const uint32_t aRow = (wm * 64 + (lane & 15)) * (FB_STRIDE * 2);
  const uint32_t aColB = ((lane >> 4) << 3) * 2;
  const uint32_t bRow = (wn * 32 + (lane & 7)) * (FB_STRIDE * 2);
  const uint32_t bColB = (((lane >> 3) & 1) << 3) * 2;
  const uint32_t bOff = (grp ? 4u : 2u) * FB_ARR;

  for (int c = 0; c < cNCC; c++) {
    int s = c % 3;
    MBAR_WAIT(sb + s * 8, (c / 3) & 1);
    if (tid == 0 && c + 2 < cNCC) {
      if (c >= 1) MBAR_WAIT(sb + 24 + ((c + 2) % 3) * 8, ((c - 1) / 3) & 1);
      issue(c + 2);
    }
    uint32_t base = sb + FB_HDR + s * FB_CHUNK;
#pragma unroll
    for (int ks = 0; ks < 2; ks++) {
      uint32_t kb = ks * 32;
      uint32_t ah[4][4], al[4][4];
#pragma unroll
      for (int mt = 0; mt < 4; mt++) {
        uint32_t ad = base + aRow + mt * 16 * (FB_STRIDE * 2) + kb + aColB;
        ldsm_x4(ah[mt], ad);
        ldsm_x4(al[mt], ad + FB_ARR);
      }
#pragma unroll
      for (int nt = 0; nt < 4; nt++) {
        uint32_t bd = base + bOff + bRow + nt * 8 * (FB_STRIDE * 2) + kb + bColB;
        uint32_t bh2[2], bl2[2];
        ldsm_x2(bh2, bd);
        ldsm_x2(bl2, bd + FB_ARR);
#pragma unroll
        for (int mt = 0; mt < 4; mt++) mma16816(acc[mt][nt], ah[mt], bh2);
#pragma unroll
        for (int mt = 0; mt < 4; mt++) mma16816(acc[mt][nt], ah[mt], bl2);
#pragma unroll
        for (int mt = 0; mt < 4; mt++) mma16816(acc[mt][nt], al[mt], bh2);
      }
    }
    if (lane == 0) MBAR_ARRIVE(sb + 24 + s * 8);
  }

#pragma unroll
  for (int mt = 0; mt < 4; mt++) {
    int mloc = wm * 64 + mt * 16 + (lane >> 2);
#pragma unroll
    for (int half = 0; half < 2; half++) {
      int m = m0 + mloc + half * 8;
      int orow = (m / rpbIn) * rpbOut + rowOff + (m % rpbIn);
#pragma unroll
      for (int nt = 0; nt < 4; nt++) {
        int n = n0 + wn * 32 + nt * 8 + (lane & 3) * 2;
        float v0 = acc[mt][nt][half * 2 + 0];
        float v1 = acc[mt][nt][half * 2 + 1];
        if (grp == 0) {
          v0 += biasK[n]; v1 += biasK[n + 1];
          *(float2*)(Kout + (size_t)orow * cHHD + n) = make_float2(v0, v1);
        } else {
          v0 += biasV[n]; v1 += biasV[n + 1];
          bf16 h0 = __float2bfloat16(v0), h1 = __float2bfloat16(v1);
          *(__nv_bfloat162*)(Vhi + (size_t)orow * cHHD + n) =
              __nv_bfloat162(h0, h1);
          *(__nv_bfloat162*)(Vlo + (size_t)orow * cHHD + n) = __nv_bfloat162(
              __float2bfloat16(v0 - __bfloat162float(h0)),
              __float2bfloat16(v1 - __bfloat162float(h1)));
        }
      }
    }
  }
}

// ---------------------------------------------------------------------------
// Generalized bulk MMA GEMM (Q, Wo, Wfc, Wcp) — unchanged R13.
// ---------------------------------------------------------------------------
#define GB_ARR 10240
#define GB_CHUNK (4 * GB_ARR)
#define GB_HDR 1024
#define GB_SMEM (GB_HDR + 2 * GB_CHUNK)

__global__ __launch_bounds__(256) void mma_gemm_bulk(
    const bf16* __restrict__ ATh, const bf16* __restrict__ ATl,
    const bf16* __restrict__ BTh, const bf16* __restrict__ BTl,
    const float* __restrict__ bias, const float* __restrict__ R,
    float* __restrict__ C, bf16* __restrict__ ChiT, bf16* __restrict__ CloT,
    int Kdim, int cN, int outKd, int relu) {
  extern __shared__ char sm[];
  const uint32_t sb = smem_u32(sm);
  const int tid = threadIdx.x, lane = tid & 31, wid = tid >> 5;
  const int wm = wid & 1, wn = wid >> 1;
  const int mb = blockIdx.y, nb = blockIdx.x;
  const int m0 = mb * 128, n0 = nb * 128;
  const int nc = Kdim >> 5;

  const char* srcs[4];
  srcs[0] = (const char*)ATh + (size_t)mb * nc * GB_ARR;
  srcs[1] = (const char*)ATl + (size_t)mb * nc * GB_ARR;
  srcs[2] = (const char*)BTh + (size_t)nb * nc * GB_ARR;
  srcs[3] = (const char*)BTl + (size_t)nb * nc * GB_ARR;

  if (tid == 0) {
    MBAR_INIT(sb + 0, 1);
    MBAR_INIT(sb + 8, 1);
    MBAR_INIT(sb + 16, 8);
    MBAR_INIT(sb + 24, 8);
  }
  __syncthreads();

  auto issue = [&](int c) {
    int s = c & 1;
    uint32_t bar = sb + s * 8;
    MBAR_EXPECT_TX(bar, GB_CHUNK);
    uint32_t dst = sb + GB_HDR + s * GB_CHUNK;
#pragma unroll
    for (int a = 0; a < 4; a++)
      bulk_g2s(dst + a * GB_ARR, srcs[a] + (size_t)c * GB_ARR, GB_ARR, bar);
  };
  if (tid == 0) issue(0);

  float acc[4][4][4];
#pragma unroll
  for (int mt = 0; mt < 4; mt++)
#pragma unroll
    for (int nt = 0; nt < 4; nt++)
#pragma unroll
      for (int j = 0; j < 4; j++) acc[mt][nt][j] = 0.f;

  const uint32_t aRow = (wm * 64 + (lane & 15)) * (FB_STRIDE * 2);
  const uint32_t aColB = ((lane >> 4) << 3) * 2;
  const uint32_t bRow = (wn * 32 + (lane & 7)) * (FB_STRIDE * 2);
  const uint32_t bColB = (((lane >> 3) & 1) << 3) * 2;

  for (int c = 0; c < nc; c++) {
    int s = c & 1;
    MBAR_WAIT(sb + s * 8, (c >> 1) & 1);
    if (tid == 0 && c + 1 < nc) {
      if (c >= 1) MBAR_WAIT(sb + 16 + ((c + 1) & 1) * 8, ((c - 1) >> 1) & 1);
      issue(c + 1);
    }
    uint32_t base = sb + GB_HDR + s * GB_CHUNK;
#pragma unroll
    for (int ks = 0; ks < 2; ks++) {
      uint32_t kb = ks * 32;
      uint32_t ah[4][4], al[4][4];
#pragma unroll
      for (int mt = 0; mt < 4; mt++) {
        uint32_t ad = base + aRow + mt * 16 * (FB_STRIDE * 2) + kb + aColB;
        ldsm_x4(ah[mt], ad);
        ldsm_x4(al[mt], ad + GB_ARR);
      }
#pragma unroll
      for (int nt = 0; nt < 4; nt++) {
        uint32_t bd =
            base + 2 * GB_ARR + bRow + nt * 8 * (FB_STRIDE * 2) + kb + bColB;
        uint32_t bh2[2], bl2[2];
        ldsm_x2(bh2, bd);
        ldsm_x2(bl2, bd + GB_ARR);
#pragma unroll
        for (int mt = 0; mt < 4; mt++) mma16816(acc[mt][nt], ah[mt], bh2);
#pragma unroll
        for (int mt = 0; mt < 4; mt++) mma16816(acc[mt][nt], ah[mt], bl2);
#pragma unroll
        for (int mt = 0; mt < 4; mt++) mma16816(acc[mt][nt], al[mt], bh2);
      }
    }
    if (lane == 0) MBAR_ARRIVE(sb + 16 + s * 8);
  }

  const int ncOut = outKd >> 5;
#pragma unroll
  for (int mt = 0; mt < 4; mt++) {
    int mloc = wm * 64 + mt * 16 + (lane >> 2);
#pragma unroll
    for (int half = 0; half < 2; half++) {
      int orow = m0 + mloc + half * 8;
#pragma unroll
      for (int nt = 0; nt < 4; nt++) {
        int n = n0 + wn * 32 + nt * 8 + (lane & 3) * 2;
        float v0 = acc[mt][nt][half * 2 + 0];
        float v1 = acc[mt][nt][half * 2 + 1];
        if (bias != nullptr) { v0 += bias[n]; v1 += bias[n + 1]; }
        if (R != nullptr) {
          float2 rv = *(const float2*)(R + (size_t)orow * cN + n);
          v0 += rv.x; v1 += rv.y;
        }
        if (relu) { v0 = fmaxf(v0, 0.f); v1 = fmaxf(v1, 0.f); }
        if (C != nullptr)
          *(float2*)(C + (size_t)orow * cN + n) = make_float2(v0, v1);
        if (ChiT != nullptr) {
          size_t off = ((size_t)(orow >> 7) * ncOut + (n >> 5)) * 5120 +
                       (orow & 127) * 40 + (n & 31);
          bf16 h0 = __float2bfloat16(v0);
          bf16 h1 = __float2bfloat16(v1);
          *(__nv_bfloat162*)(ChiT + off) = __nv_bfloat162(h0, h1);
          *(__nv_bfloat162*)(CloT + off) = __nv_bfloat162(
              __float2bfloat16(v0 - __bfloat162float(h0)),
              __float2bfloat16(v1 - __bfloat162float(h1)));
        }
      }
    }
  }
}

// ---------------------------------------------------------------------------
// FUSED flash-style attention: per (b,h) CTA. Q-LN once; loop 37 chunks:
// cp.async K(fp32)+V(hi/lo), K-LN, QK^T 3-term MMA, online softmax,
// P hi/lo -> smem, O rescale, PV 3-term MMA; final O/l -> tiled att.
// Warp w: rows [(w>>1)*16, +16); QK cols (w&1)*32; PV d-cols (w&1)*48.
// ---------------------------------------------------------------------------
#define FA_SQH 0
#define FA_SQL 13312
#define FA_SKH 26624
#define FA_SKL 39936
#define FA_SPH 53248
#define FA_SPL 62464
#define FA_SV 71680    /* + buf*26624; Vl at +13312 */
#define FA_SKRAW 124928 /* + buf*24576 */
#define FA_REDM 174080  /* 2 x 64 floats */
#define FA_REDS 174592  /* 2 x 64 floats */
#define FA_SMEM 175104

__global__ __launch_bounds__(256) void fused_attention(
    const float* __restrict__ Q, const float* __restrict__ K,
    const bf16* __restrict__ Vh, const bf16* __restrict__ Vl,
    const float* __restrict__ qg, const float* __restrict__ qb,
    const float* __restrict__ kg, const float* __restrict__ kb,
    bf16* __restrict__ OhiT, bf16* __restrict__ OloT) {
  extern __shared__ char sm[];
  const uint32_t sb = smem_u32(sm);
  const int tid = threadIdx.x, lane = tid & 31, wid = tid >> 5;
  const int bh = blockIdx.x, b = bh >> 4, h = bh & 15;
  const int wm = wid >> 1, wn = wid & 1;
  const float scale = 0.102062072615966f;  // 96^-0.5, folded into Q

  const float gq0 = qg[lane], gq1 = qg[lane + 32], gq2 = qg[lane + 64];
  const float bq0 = qb[lane], bq1 = qb[lane + 32], bq2 = qb[lane + 64];
  const float gk0 = kg[lane], gk1 = kg[lane + 32], gk2 = kg[lane + 64];
  const float bk0 = kb[lane], bk1 = kb[lane + 32], bk2 = kb[lane + 64];

  bf16* qh = (bf16*)(sm + FA_SQH);
  bf16* ql = (bf16*)(sm + FA_SQL);
  bf16* kh = (bf16*)(sm + FA_SKH);
  bf16* kl = (bf16*)(sm + FA_SKL);
  bf16* ph = (bf16*)(sm + FA_SPH);
  bf16* pl = (bf16*)(sm + FA_SPL);
  float* redm = (float*)(sm + FA_REDM);
  float* reds = (float*)(sm + FA_REDS);

  auto prefetch = [&](int ct, int buf) {
    int t0 = ct * 64;
    uint32_t vbase = sb + FA_SV + buf * 26624;
#pragma unroll
    for (int it = 0; it < 3; it++) {  // V: 768 16B units per array
      int e = tid + it * 256;
      int r = e / 12, u = e % 12;
      uint32_t so = r * 208 + u * 16;
      size_t vo = (size_t)(b * cT + t0 + r) * cHHD + h * cHD + u * 8;
      cp_async16(vbase + so, Vh + vo);
      cp_async16(vbase + 13312 + so, Vl + vo);
    }
    uint32_t kbase = sb + FA_SKRAW + buf * 24576;
#pragma unroll
    for (int it = 0; it < 6; it++) {  // K raw fp32: 1536 16B units
      int e = tid + it * 256;
      int r = e / 24, u = e % 24;
      cp_async16(kbase + r * 384 + u * 16,
                 K + (size_t)(b * cT + t0 + r) * cHHD + h * cHD + u * 4);
    }
    CP_COMMIT();
  };

  prefetch(0, 0);

  // Q LN + hi/lo split (scale folded), warp handles rows wid + rr*8
#pragma unroll
  for (int rr = 0; rr < 8; rr++) {
    int r = wid + rr * 8;
    const float* xr = Q + (size_t)(b * cL + r) * cHHD + h * cHD;
    float v0 = xr[lane], v1 = xr[lane + 32], v2 = xr[lane + 64];
    float s = v0 + v1 + v2, s2 = v0 * v0 + v1 * v1 + v2 * v2;
    for (int o = 16; o; o >>= 1) {
      s += __shfl_xor_sync(~0u, s, o);
      s2 += __shfl_xor_sync(~0u, s2, o);
    }
    float mean = s * (1.f / 96.f);
    float rstd = rsqrtf(s2 * (1.f / 96.f) - mean * mean + cEPS);
    float y0 = ((v0 - mean) * rstd * gq0 + bq0) * scale;
    float y1 = ((v1 - mean) * rstd * gq1 + bq1) * scale;
    float y2 = ((v2 - mean) * rstd * gq2 + bq2) * scale;
    bf16 h0 = __float2bfloat16(y0), h1 = __float2bfloat16(y1),
         h2 = __float2bfloat16(y2);
    int rb = r * 104;
    qh[rb + lane] = h0; qh[rb + lane + 32] = h1; qh[rb + lane + 64] = h2;
    ql[rb + lane] = __float2bfloat16(y0 - __bfloat162float(h0));
    ql[rb + lane + 32] = __float2bfloat16(y1 - __bfloat162float(h1));
    ql[rb + lane + 64] = __float2bfloat16(y2 - __bfloat162float(h2));
  }

  // per-thread softmax state for rows r0, r1
  const int r0 = wm * 16 + (lane >> 2);
  const int r1 = r0 + 8;
  float m0s = -1e30f, m1s = -1e30f, l0s = 0.f, l1s = 0.f;
  float acc[6][4];
#pragma unroll
  for (int nt = 0; nt < 6; nt++)
#pragma unroll
    for (int j = 0; j < 4; j++) acc[nt][j] = 0.f;

  for (int ct = 0; ct < 37; ct++) {
    int buf = ct & 1;
    CP_WAIT(0);
    __syncthreads();  // chunk data ready; all prior smem reads done
    if (ct + 1 < 37) prefetch(ct + 1, buf ^ 1);

    // K LN -> kh/kl
    const float* kr = (const float*)(sm + FA_SKRAW + buf * 24576);
#pragma unroll
    for (int rr = 0; rr < 8; rr++) {
      int r = wid + rr * 8;
      float v0 = kr[r * 96 + lane], v1 = kr[r * 96 + lane + 32],
            v2 = kr[r * 96 + lane + 64];
      float s = v0 + v1 + v2, s2 = v0 * v0 + v1 * v1 + v2 * v2;
      for (int o = 16; o; o >>= 1) {
        s += __shfl_xor_sync(~0u, s, o);
        s2 += __shfl_xor_sync(~0u, s2, o);
      }
      float mean = s * (1.f / 96.f);
      float rstd = rsqrtf(s2 * (1.f / 96.f) - mean * mean + cEPS);
      float y0 = (v0 - mean) * rstd * gk0 + bk0;
      float y1 = (v1 - mean) * rstd * gk1 + bk1;
      float y2 = (v2 - mean) * rstd * gk2 + bk2;
      bf16 h0 = __float2bfloat16(y0), h1 = __float2bfloat16(y1),
           h2 = __float2bfloat16(y2);
      int rb = r * 104;
      kh[rb + lane] = h0; kh[rb + lane + 32] = h1; kh[rb + lane + 64] = h2;
      kl[rb + lane] = __float2bfloat16(y0 - __bfloat162float(h0));
      kl[rb + lane + 32] = __float2bfloat16(y1 - __bfloat162float(h1));
      kl[rb + lane + 64] = __float2bfloat16(y2 - __bfloat162float(h2));
    }
    __syncthreads();

    // QK^T : sacc[nt][j], rows r0/r1, cols wn*32 + nt*8 + (lane&3)*2
    float sacc[4][4];
#pragma unroll
    for (int nt = 0; nt < 4; nt++)
#pragma unroll
      for (int j = 0; j < 4; j++) sacc[nt][j] = 0.f;
#pragma unroll
    for (int ks = 0; ks < 6; ks++) {
      uint32_t kbo = ks * 32;
      uint32_t ah[4], al2[4];
      uint32_t ad = sb + FA_SQH + (wm * 16 + (lane & 15)) * 208 + kbo +
                    (lane >> 4) * 16;
      ldsm_x4(ah, ad);
      ldsm_x4(al2, ad + (FA_SQL - FA_SQH));
#pragma unroll
      for (int nt = 0; nt < 4; nt++) {
        uint32_t bd = sb + FA_SKH +
                      (wn * 32 + nt * 8 + (lane & 7)) * 208 + kbo +
                      ((lane >> 3) & 1) * 16;
        uint32_t bh2[2], bl2[2];
        ldsm_x2(bh2, bd);
        ldsm_x2(bl2, bd + (FA_SKL - FA_SKH));
        mma16816(sacc[nt], ah, bh2);
        mma16816(sacc[nt], ah, bl2);
        mma16816(sacc[nt], al2, bh2);
      }
    }

    // online softmax: row max (2-warp combine via smem)
    float tm0 = -1e30f, tm1 = -1e30f;
#pragma unroll
    for (int nt = 0; nt < 4; nt++) {
      tm0 = fmaxf(tm0, fmaxf(sacc[nt][0], sacc[nt][1]));
      tm1 = fmaxf(tm1, fmaxf(sacc[nt][2], sacc[nt][3]));
    }
    tm0 = fmaxf(tm0, __shfl_xor_sync(~0u, tm0, 1));
    tm0 = fmaxf(tm0, __shfl_xor_sync(~0u, tm0, 2));
    tm1 = fmaxf(tm1, __shfl_xor_sync(~0u, tm1, 1));
    tm1 = fmaxf(tm1, __shfl_xor_sync(~0u, tm1, 2));
    if ((lane & 3) == 0) {
      redm[wn * 64 + r0] = tm0;
      redm[wn * 64 + r1] = tm1;
    }
    __syncthreads();
    float mn0 = fmaxf(m0s, fmaxf(redm[r0], redm[64 + r0]));
    float mn1 = fmaxf(m1s, fmaxf(redm[r1], redm[64 + r1]));
    float sc0 = fexp(m0s - mn0), sc1 = fexp(m1s - mn1);
    m0s = mn0; m1s = mn1;

    // exp + P smem write (hi/lo) + partial sums
    float ts0 = 0.f, ts1 = 0.f;
#pragma unroll
    for (int nt = 0; nt < 4; nt++) {
      float p0 = fexp(sacc[nt][0] - mn0);
      float p1 = fexp(sacc[nt][1] - mn0);
      float p2 = fexp(sacc[nt][2] - mn1);
      float p3 = fexp(sacc[nt][3] - mn1);
      ts0 += p0 + p1;
      ts1 += p2 + p3;
      int col = wn * 32 + nt * 8 + (lane & 3) * 2;
      bf16 h0 = __float2bfloat16(p0), h1 = __float2bfloat16(p1);
      bf16 h2 = __float2bfloat16(p2), h3 = __float2bfloat16(p3);
      *(__nv_bfloat162*)(ph + r0 * 72 + col) = __nv_bfloat162(h0, h1);
      *(__nv_bfloat162*)(ph + r1 * 72 + col) = __nv_bfloat162(h2, h3);
      *(__nv_bfloat162*)(pl + r0 * 72 + col) = __nv_bfloat162(
          __float2bfloat16(p0 - __bfloat162float(h0)),
          __float2bfloat16(p1 - __bfloat162float(h1)));
      *(__nv_bfloat162*)(pl + r1 * 72 + col) = __nv_bfloat162(
          __float2bfloat16(p2 - __bfloat162float(h2)),
          __float2bfloat16(p3 - __bfloat162float(h3)));
    }
    ts0 += __shfl_xor_sync(~0u, ts0, 1);
    ts0 += __shfl_xor_sync(~0u, ts0, 2);
    ts1 += __shfl_xor_sync(~0u, ts1, 1);
    ts1 += __shfl_xor_sync(~0u, ts1, 2);
    if ((lane & 3) == 0) {
      reds[wn * 64 + r0] = ts0;
      reds[wn * 64 + r1] = ts1;
    }
    __syncthreads();  // also makes all P writes visible
    l0s = l0s * sc0 + reds[r0] + reds[64 + r0];
    l1s = l1s * sc1 + reds[r1] + reds[64 + r1];
#pragma unroll
    for (int nt = 0; nt < 6; nt++) {
      acc[nt][0] *= sc0; acc[nt][1] *= sc0;
      acc[nt][2] *= sc1; acc[nt][3] *= sc1;
    }

    // PV: O += P(hi/lo) @ V(hi/lo)  (rows r0/r1, d-cols wn*48 + nt*8)
    uint32_t vbase = sb + FA_SV + buf * 26624;
#pragma unroll
    for (int ks = 0; ks < 4; ks++) {
      uint32_t ap[4], apl[4];
      uint32_t aa = sb + FA_SPH + (wm * 16 + (lane & 15)) * 144 + ks * 32 +
                    (lane >> 4) * 16;
      ldsm_x4(ap, aa);
      ldsm_x4(apl, aa + (FA_SPL - FA_SPH));
#pragma unroll
      for (int nt = 0; nt < 6; nt++) {
        uint32_t ba = vbase +
                      (ks * 16 + ((lane >> 3) & 1) * 8 + (lane & 7)) * 208 +
                      (wn * 48 + nt * 8) * 2;
        uint32_t bv[2], blv[2];
        ldsm_x2_trans(bv, ba);
        ldsm_x2_trans(blv, ba + 13312);
        mma16816(acc[nt], ap, bv);
        mma16816(acc[nt], ap, blv);
        mma16816(acc[nt], apl, bv);
      }
    }
  }

  // epilogue: O / l -> tiled att blob
  float inv0 = 1.f / l0s, inv1 = 1.f / l1s;
#pragma unroll
  for (int half = 0; half < 2; half++) {
    int row = b * cL + wm * 16 + (lane >> 2) + half * 8;
    float inv = half ? inv1 : inv0;
#pragma unroll
    for (int nt = 0; nt < 6; nt++) {
      int col = h * cHD + wn * 48 + nt * 8 + (lane & 3) * 2;
      float v0 = acc[nt][half * 2] * inv, v1 = acc[nt][half * 2 + 1] * inv;
      bf16 h0 = __float2bfloat16(v0), h1 = __float2bfloat16(v1);
      size_t off = ((size_t)(row >> 7) * 48 + (col >> 5)) * 5120 +
                   (row & 127) * 40 + (col & 31);
      *(__nv_bfloat162*)(OhiT + off) = __nv_bfloat162(h0, h1);
      *(__nv_bfloat162*)(OloT + off) = __nv_bfloat162(
          __float2bfloat16(v0 - __bfloat162float(h0)),
          __float2bfloat16(v1 - __bfloat162float(h1)));
    }
  }
}

// ---------------------------------------------------------------------------
// LN (no affine) -> TILED bf16 hi/lo blob (row length cD, nc=40)
// ---------------------------------------------------------------------------
__global__ void ln_tiled_kernel(const float* __restrict__ x,
                                bf16* __restrict__ hi, bf16* __restrict__ lo) {
  int row = blockIdx.x;
  const float* xr = x + (size_t)row * cD;
  float s = 0.f, s2 = 0.f;
  for (int c = threadIdx.x; c < cD; c += 256) {
    float v = xr[c];
    s += v; s2 += v * v;
  }
  __shared__ float sh[64];
  for (int o = 16; o; o >>= 1) {
    s += __shfl_xor_sync(~0u, s, o);
    s2 += __shfl_xor_sync(~0u, s2, o);
  }
  int w = threadIdx.x >> 5, lane = threadIdx.x & 31;
  if (lane == 0) { sh[w] = s; sh[w + 32] = s2; }
  __syncthreads();
  if (w == 0) {
    s = (lane < 8) ? sh[lane] : 0.f;
    s2 = (lane < 8) ? sh[lane + 32] : 0.f;
    for (int o = 16; o; o >>= 1) {
      s += __shfl_xor_sync(~0u, s, o);
      s2 += __shfl_xor_sync(~0u, s2, o);
    }
    if (lane == 0) { sh[0] = s; sh[1] = s2; }
  }
  __syncthreads();
  float mean = sh[0] * (1.f / cD);
  float rstd = rsqrtf(sh[1] * (1.f / cD) - mean * mean + cEPS);
  size_t rowbase = (size_t)(row >> 7) * cNCC * 5120 + (size_t)(row & 127) * 40;
  for (int c = threadIdx.x; c < cD; c += 256) {
    float v = (xr[c] - mean) * rstd;
    bf16 h = __float2bfloat16(v);
    size_t off = rowbase + (size_t)(c >> 5) * 5120 + (c & 31);
    hi[off] = h;
    lo[off] = __float2bfloat16(v - __bfloat162float(h));
  }
}

// ---------------------------------------------------------------------------
// Tiled weight prep (any Kdim/Nw): Wt blob + rank-1 bias
// ---------------------------------------------------------------------------
__global__ void wprep_tiled_kernel(const float* __restrict__ W,
                                   const float* __restrict__ g,
                                   const float* __restrict__ b,
                                   bf16* __restrict__ Whi,
                                   bf16* __restrict__ Wlo,
                                   float* __restrict__ bias, int Kdim, int Nw) {
  int n = blockIdx.x;
  int nc = Kdim >> 5;
  float bs = 0.f;
  size_t rowbase = (size_t)(n >> 7) * nc * 5120 + (size_t)(n & 127) * 40;
  for (int k = threadIdx.x; k < Kdim; k += 256) {
    float w = W[(size_t)k * Nw + n];
    float v = (g != nullptr) ? g[k] * w : w;
    bf16 h = __float2bfloat16(v);
    size_t off = rowbase + (size_t)(k >> 5) * 5120 + (k & 31);
    Whi[off] = h;
    Wlo[off] = __float2bfloat16(v - __bfloat162float(h));
    if (b != nullptr) bs += b[k] * w;
  }
  if (bias != nullptr) {
    __shared__ float sh[8];
    for (int o = 16; o; o >>= 1) bs += __shfl_xor_sync(~0u, bs, o);
    int w8 = threadIdx.x >> 5, lane = threadIdx.x & 31;
    if (lane == 0) sh[w8] = bs;
    __syncthreads();
    if (threadIdx.x == 0) {
      float t = 0.f;
      for (int i = 0; i < 8; i++) t += sh[i];
      bias[n] = t;
    }
  }
}

// ---------------------------------------------------------------------------
// Broadcast latents
// ---------------------------------------------------------------------------
__global__ void bcast_latents_kernel(const float* __restrict__ lat,
                                     float* __restrict__ out) {
  int idx = blockIdx.x * 256 + threadIdx.x;
  out[idx] = lat[idx % (cL * cD)];
}

// ---------------------------------------------------------------------------
// Final LayerNorm with affine
// ---------------------------------------------------------------------------
__global__ void ln_rows_kernel(const float* __restrict__ x,
                               float* __restrict__ y,
                               const float* __restrict__ g,
                               const float* __restrict__ b) {
  int row = blockIdx.x;
  const float* xr = x + (size_t)row * cD;
  float* yr = y + (size_t)row * cD;
  float s = 0.f, s2 = 0.f;
  for (int c = threadIdx.x; c < cD; c += 256) {
    float v = xr[c];
    s += v; s2 += v * v;
  }
  __shared__ float sh[64];
  for (int o = 16; o; o >>= 1) {
    s += __shfl_xor_sync(~0u, s, o);
    s2 += __shfl_xor_sync(~0u, s2, o);
  }
  int w = threadIdx.x >> 5, lane = threadIdx.x & 31;
  if (lane == 0) { sh[w] = s; sh[w + 32] = s2; }
  __syncthreads();
  if (w == 0) {
    s = (lane < 8) ? sh[lane] : 0.f;
    s2 = (lane < 8) ? sh[lane + 32] : 0.f;
    for (int o = 16; o; o >>= 1) {
      s += __shfl_xor_sync(~0u, s, o);
      s2 += __shfl_xor_sync(~0u, s2, o);
    }
    if (lane == 0) { sh[0] = s; sh[1] = s2; }
  }
  __syncthreads();
  float mean = sh[0] * (1.f / cD);
  float rstd = rsqrtf(sh[1] * (1.f / cD) - mean * mean + cEPS);
  for (int c = threadIdx.x; c < cD; c += 256)
    yr[c] = (xr[c] - mean) * rstd * g[c] + b[c];
}

// ---------------------------------------------------------------------------
// Host orchestration
// ---------------------------------------------------------------------------
extern "C" void kernel_launch(void* const* d_in, const int* in_sizes, int n_in,
                              void* d_out, int out_size) {
  (void)in_sizes; (void)n_in; (void)out_size;
  const float* context = (const float*)d_in[0];
  const float* latents = (const float*)d_in[1];
  const float* ctx_g = (const float*)d_in[2];
  const float* ctx_b = (const float*)d_in[3];
  const float* lat_g = (const float*)d_in[4];
  const float* lat_b = (const float*)d_in[5];
  const float* q_g = (const float*)d_in[6];
  const float* q_b = (const float*)d_in[7];
  const float* k_g = (const float*)d_in[8];
  const float* k_b = (const float*)d_in[9];
  const float* Wq = (const float*)d_in[10];
  const float* Wk = (const float*)d_in[11];
  const float* Wv = (const float*)d_in[12];
  const float* Wo = (const float*)d_in[13];
  const float* mlp_g = (const float*)d_in[14];
  const float* mlp_b = (const float*)d_in[15];
  const float* Wfc = (const float*)d_in[16];
  const float* Wcp = (const float*)d_in[17];
  const float* f_g = (const float*)d_in[18];
  const float* f_b = (const float*)d_in[19];
  float* out = (float*)d_out;

#define SYM(var, sym) cudaGetSymbolAddress((void**)&var, sym)
  bf16 *ctxTh, *ctxTl, *lnTh, *lnTl, *attTh, *attTl, *mlpTh, *mlpTl;
  bf16 *vhi, *vlo;
  bf16 *wkcTh, *wkcTl, *wvcTh, *wvcTl, *wqTh, *wqTl, *wklTh, *wklTl, *wvlTh,
      *wvlTl, *woTh, *woTl, *wfcTh, *wfcTl, *wcpTh, *wcpTl;
  float *bQ, *bKc, *bKl, *bVc, *bVl, *bFc;
  float *lat, *Qp, *Kp;
  SYM(ctxTh, g_ctxT_hi); SYM(ctxTl, g_ctxT_lo);
  SYM(lnTh, g_latlnT_hi); SYM(lnTl, g_latlnT_lo);
  SYM(attTh, g_attT_hi); SYM(attTl, g_attT_lo);
  SYM(mlpTh, g_mlpT_hi); SYM(mlpTl, g_mlpT_lo);
  SYM(vhi, g_V_hi); SYM(vlo, g_V_lo);
  SYM(wkcTh, g_wkcT_hi); SYM(wkcTl, g_wkcT_lo);
  SYM(wvcTh, g_wvcT_hi); SYM(wvcTl, g_wvcT_lo);
  SYM(wqTh, g_wqT_hi); SYM(wqTl, g_wqT_lo);
  SYM(wklTh, g_wklT_hi); SYM(wklTl, g_wklT_lo);
  SYM(wvlTh, g_wvlT_hi); SYM(wvlTl, g_wvlT_lo);
  SYM(woTh, g_woT_hi); SYM(woTl, g_woT_lo);
  SYM(wfcTh, g_wfcT_hi); SYM(wfcTl, g_wfcT_lo);
  SYM(wcpTh, g_wcpT_hi); SYM(wcpTl, g_wcpT_lo);
  SYM(bQ, g_biasQ); SYM(bKc, g_biasKc); SYM(bKl, g_biasKl);
  SYM(bVc, g_biasVc); SYM(bVl, g_biasVl); SYM(bFc, g_biasFc);
  SYM(lat, g_lat); SYM(Qp, g_Q); SYM(Kp, g_K);
#undef SYM

  cudaFuncSetAttribute(fused_kv_bulk,
                       cudaFuncAttributeMaxDynamicSharedMemorySize, FB_SMEM);
  cudaFuncSetAttribute(mma_gemm_bulk,
                       cudaFuncAttributeMaxDynamicSharedMemorySize, GB_SMEM);
  cudaFuncSetAttribute(fused_attention,
                       cudaFuncAttributeMaxDynamicSharedMemorySize, FA_SMEM);

  dim3 kvGridCtx(12, cMB);
  dim3 kvGridLat(12, cML / 128);

  // launch 0: LN(context) -> tiled (once)
  ln_tiled_kernel<<<cMCTX, 256>>>(context, ctxTh, ctxTl);
  // launches 1,2: layer-0 ctx weight preps
  wprep_tiled_kernel<<<cHHD, 256>>>(Wk, ctx_g, ctx_b, wkcTh, wkcTl, bKc, cD,
                                    cHHD);
  wprep_tiled_kernel<<<cHHD, 256>>>(Wv, ctx_g, ctx_b, wvcTh, wvcTl, bVc, cD,
                                    cHHD);
  // launch 3: layer-0 fused ctx K+V projection  << ncu capture slot >>
  fused_kv_bulk<<<kvGridCtx, 512, FB_SMEM>>>(ctxTh, ctxTl, wkcTh, wkcTl, wvcTh,
                                             wvcTl, bKc, bVc, Kp, vhi, vlo, cS,
                                             cT, 0);
  bcast_latents_kernel<<<(cML * cD) / 256, 256>>>(latents, lat);

  for (int i = 0; i < cDEPTH; i++) {
    const float* Wq_i = Wq + (size_t)i * cD * cHHD;
    const float* Wk_i = Wk + (size_t)i * cD * cHHD;
    const float* Wv_i = Wv + (size_t)i * cD * cHHD;
    const float* Wo_i = Wo + (size_t)i * cHHD * cD;
    const float* Wfc_i = Wfc + (size_t)i * cD * cI;
    const float* Wcp_i = Wcp + (size_t)i * cI * cD;
    const float* lg = lat_g + i * cD;
    const float* lb = lat_b + i * cD;

    if (i > 0) {
      wprep_tiled_kernel<<<cHHD, 256>>>(Wk_i, ctx_g + i * cD, ctx_b + i * cD,
                                        wkcTh, wkcTl, bKc, cD, cHHD);
      wprep_tiled_kernel<<<cHHD, 256>>>(Wv_i, ctx_g + i * cD, ctx_b + i * cD,
                                        wvcTh, wvcTl, bVc, cD, cHHD);
      fused_kv_bulk<<<kvGridCtx, 512, FB_SMEM>>>(ctxTh, ctxTl, wkcTh, wkcTl,
                                                 wvcTh, wvcTl, bKc, bVc, Kp,
                                                 vhi, vlo, cS, cT, 0);
    }

    // LN(latents) -> tiled hi/lo (affine folded into weights)
    ln_tiled_kernel<<<cML, 256>>>(lat, lnTh, lnTl);

    wprep_tiled_kernel<<<cHHD, 256>>>(Wq_i, lg, lb, wqTh, wqTl, bQ, cD, cHHD);
    wprep_tiled_kernel<<<cHHD, 256>>>(Wk_i, lg, lb, wklTh, wklTl, bKl, cD,
                                      cHHD);
    wprep_tiled_kernel<<<cHHD, 256>>>(Wv_i, lg, lb, wvlTh, wvlTl, bVl, cD,
                                      cHHD);

    // Q (fp32 out; per-head LN fused into attention)
    mma_gemm_bulk<<<dim3(12, 16), 256, GB_SMEM>>>(
        lnTh, lnTl, wqTh, wqTl, bQ, nullptr, Qp, nullptr, nullptr, cD, cHHD,
        cHHD, 0);
    // latent K+V rows appended at offset cS
    fused_kv_bulk<<<kvGridLat, 512, FB_SMEM>>>(lnTh, lnTl, wklTh, wklTl, wvlTh,
                                               wvlTl, bKl, bVl, Kp, vhi, vlo,
                                               cL, cT, cS);

    // fused flash-style attention (LN+QK+softmax+PV), att written tiled
    fused_attention<<<cB * cH, 256, FA_SMEM>>>(
        Qp, Kp, vhi, vlo, q_g + i * cHD, q_b + i * cHD, k_g + i * cHD,
        k_b + i * cHD, attTh, attTl);

    // lat = att @ Wo + lat
    wprep_tiled_kernel<<<cD, 256>>>(Wo_i, nullptr, nullptr, woTh, woTl,
                                    nullptr, cHHD, cD);
    mma_gemm_bulk<<<dim3(10, 16), 256, GB_SMEM>>>(
        attTh, attTl, woTh, woTl, nullptr, lat, lat, nullptr, nullptr, cHHD,
        cD, cD, 0);

    // MLP
    ln_tiled_kernel<<<cML, 256>>>(lat, lnTh, lnTl);
    wprep_tiled_kernel<<<cI, 256>>>(Wfc_i, mlp_g + i * cD, mlp_b + i * cD,
                                    wfcTh, wfcTl, bFc, cD, cI);
    mma_gemm_bulk<<<dim3(40, 16), 256, GB_SMEM>>>(
        lnTh, lnTl, wfcTh, wfcTl, bFc, nullptr, nullptr, mlpTh, mlpTl, cD, cI,
        cI, 1);
    wprep_tiled_kernel<<<cD, 256>>>(Wcp_i, nullptr, nullptr, wcpTh, wcpTl,
                                    nullptr, cI, cD);
    mma_gemm_bulk<<<dim3(10, 16), 256, GB_SMEM>>>(
        mlpTh, mlpTl, wcpTh, wcpTl, nullptr, lat, lat, nullptr, nullptr, cI,
        cD, cD, 0);
  }

  ln_rows_kernel<<<cML, 256>>>(lat, out, f_g, f_b);
}